// round 15
// baseline (speedup 1.0000x reference)
#include <cuda_runtime.h>
#include <cstdint>

// ---------------- problem constants ----------------
#define B_    256
#define P_    512
#define D_    16
#define DIN   17          // D+1 (particle dims + weight feature)
#define H_    256
#define G3    768         // 3*H
#define ACT   8
#define NCRIT 2
#define HID_  256
#define INM   265         // H + A + 1

// ---------------- GRU cluster kernel config ----------------
#define CS    4           // cluster size
#define JC    64          // hidden columns owned per CTA (H/CS)
#define BC    8           // batch rows per cluster
#define NCL   32          // clusters (NCL*BC == B_)
#define TPB   256

#define WP    260         // padded pitch (floats) for weight & h rows

#define OFF_W   0                         // [3][JC][WP]  gate weights (k contiguous)
#define OFF_WI  (3*JC*WP)                 // [3][DIN][JC] input weights (jl contiguous)
#define OFF_BI  (OFF_WI + 3*DIN*JC)       // [3][JC] input biases
#define OFF_BN  (OFF_BI + 3*JC)           // [JC] bn
#define OFF_H   (OFF_BN + JC)             // [2][BC][WP] double-buffered hidden state
#define OFF_X   (OFF_H + 2*BC*WP)         // [2][BC][20] double-buffered x features
#define SMEM_FLOATS (OFF_X + 2*BC*20)     // 57920 floats
#define SMEM_BYTES  (SMEM_FLOATS*4)       // 231680 B  (<= 232448 opt-in)

__device__ float g_enc[B_*H_];            // GRU final hidden, handed to MLP kernel

// ---------------- helpers ----------------
__device__ __forceinline__ void fma2(unsigned long long &acc,
                                     unsigned long long a,
                                     unsigned long long b) {
    asm volatile("fma.rn.f32x2 %0, %1, %2, %0;" : "+l"(acc) : "l"(a), "l"(b));
}

__device__ __forceinline__ float f2sum(unsigned long long a) {
    float lo, hi;
    asm("mov.b64 {%0, %1}, %2;" : "=f"(lo), "=f"(hi) : "l"(a));
    return lo + hi;
}

__device__ __forceinline__ float sigf(float x) {
    return 1.0f / (1.0f + __expf(-x));
}
__device__ __forceinline__ float tanh_f(float x) {
    // tanh(x) = 1 - 2/(exp(2x)+1): exact saturation at +-inf, ~1e-6 rel err
    return 1.0f - 2.0f / (__expf(2.0f * x) + 1.0f);
}

__device__ __forceinline__ void st_remote(uint32_t laddr, uint32_t rank, float v) {
    uint32_t ra;
    asm volatile("mapa.shared::cluster.u32 %0, %1, %2;" : "=r"(ra) : "r"(laddr), "r"(rank));
    asm volatile("st.shared::cluster.f32 [%0], %1;" :: "r"(ra), "f"(v));
}

__device__ __forceinline__ void cluster_sync_() {
    asm volatile("barrier.cluster.arrive.aligned;" ::: "memory");
    asm volatile("barrier.cluster.wait.aligned;" ::: "memory");
}

// =====================================================================
// Kernel 1: GRU recurrence.
// Cluster of 4 CTAs; CTA `rank` owns gate columns [64*rank, 64*rank+64)
// for 8 batch rows; weights SMEM-resident; h exchanged via DSMEM each step.
// Thread map: tid = jl*4 + tg ; thread handles column jl, batch rows 2tg, 2tg+1.
// =====================================================================
__global__ void __launch_bounds__(TPB, 1) __cluster_dims__(CS, 1, 1)
gru_kernel(const float* __restrict__ particles,  // [B,P,D]
           const float* __restrict__ pw,         // [B,P]
           const float* __restrict__ Wi,         // [DIN, 3H]
           const float* __restrict__ bi,         // [3H]
           const float* __restrict__ Whrz,       // [H, 2H]
           const float* __restrict__ Whn,        // [H, H]
           const float* __restrict__ bn)         // [H]
{
    extern __shared__ float sm[];
    const int tid   = threadIdx.x;
    const int rank  = blockIdx.x & (CS - 1);
    const int cid   = blockIdx.x >> 2;
    const int jbase = rank * JC;
    const int cbase = cid * BC;

    // ---- load owned weight columns (one-time) ----
    for (int idx = tid; idx < JC * H_; idx += TPB) {
        int k = idx >> 6, jl = idx & 63;
        sm[OFF_W + jl * WP + k]            = Whrz[k * (2*H_) + jbase + jl];        // r
        sm[OFF_W + (JC + jl) * WP + k]     = Whrz[k * (2*H_) + H_ + jbase + jl];   // z
        sm[OFF_W + (2*JC + jl) * WP + k]   = Whn [k * H_ + jbase + jl];            // n
    }
    for (int idx = tid; idx < 3 * DIN * JC; idx += TPB) {
        int jl = idx & 63; int rem = idx >> 6;
        int g = rem / DIN, d = rem % DIN;
        sm[OFF_WI + (g * DIN + d) * JC + jl] = Wi[d * G3 + g * H_ + jbase + jl];
    }
    if (tid < 3 * JC) {
        int g = tid >> 6, jl = tid & 63;
        sm[OFF_BI + tid] = bi[g * H_ + jbase + jl];
    }
    if (tid < JC) sm[OFF_BN + tid] = bn[jbase + tid];
    for (int idx = tid; idx < BC * WP; idx += TPB) sm[OFF_H + idx] = 0.0f;  // h0 = 0
    if (tid < BC * DIN) {   // stage x for p = 0
        int bb = tid / DIN, d = tid % DIN;
        int gb = cbase + bb;
        sm[OFF_X + bb * 20 + d] = (d < D_) ? particles[gb * (P_ * D_) + d]
                                           : pw[gb * P_];
    }
    __syncthreads();
    cluster_sync_();

    const int jl = tid >> 2, tg = tid & 3;
    const int b0 = tg * 2, b1 = b0 + 1;
    const int wR = OFF_W + jl * WP;
    const int wZ = OFF_W + (JC + jl) * WP;
    const int wN = OFF_W + (2*JC + jl) * WP;
    const uint32_t smem_base = (uint32_t)__cvta_generic_to_shared(sm);

    const float bir = sm[OFF_BI + jl];
    const float biz = sm[OFF_BI + JC + jl];
    const float bin = sm[OFF_BI + 2*JC + jl];
    const float bnv = sm[OFF_BN + jl];

    for (int p = 0; p < P_; ++p) {
        const int cur = p & 1, nxt = cur ^ 1;

        // prefetch x for step p+1 into registers (hidden under k-loop)
        float xpre = 0.0f; int pb = 0, pd = 0;
        if (p + 1 < P_ && tid < BC * DIN) {
            pb = tid / DIN; pd = tid % DIN;
            int gb = cbase + pb;
            xpre = (pd < D_) ? particles[gb * (P_ * D_) + (p + 1) * D_ + pd]
                             : pw[gb * P_ + (p + 1)];
        }

        // ---- input-gate contributions: gi = x @ Wi + bi (17-dot) ----
        float gr0 = bir, gz0 = biz, gn0 = bin;
        float gr1 = bir, gz1 = biz, gn1 = bin;
        const float* xc0 = &sm[OFF_X + (cur * BC + b0) * 20];
        const float* xc1 = &sm[OFF_X + (cur * BC + b1) * 20];
        #pragma unroll
        for (int d = 0; d < DIN; ++d) {
            float wr = sm[OFF_WI + d * JC + jl];
            float wz = sm[OFF_WI + (DIN + d) * JC + jl];
            float wn = sm[OFF_WI + (2*DIN + d) * JC + jl];
            float x0 = xc0[d], x1 = xc1[d];
            gr0 += x0 * wr; gz0 += x0 * wz; gn0 += x0 * wn;
            gr1 += x1 * wr; gz1 += x1 * wz; gn1 += x1 * wn;
        }

        // ---- recurrent dots over k with packed f32x2 FMA ----
        unsigned long long ar0 = 0, az0 = 0, an0 = 0;
        unsigned long long ar1 = 0, az1 = 0, an1 = 0;
        const int h0off = OFF_H + (cur * BC + b0) * WP;
        const int h1off = OFF_H + (cur * BC + b1) * WP;
        #pragma unroll 4
        for (int k = 0; k < H_; k += 4) {
            ulonglong2 vr = *reinterpret_cast<const ulonglong2*>(&sm[wR + k]);
            ulonglong2 vz = *reinterpret_cast<const ulonglong2*>(&sm[wZ + k]);
            ulonglong2 vn = *reinterpret_cast<const ulonglong2*>(&sm[wN + k]);
            ulonglong2 ha = *reinterpret_cast<const ulonglong2*>(&sm[h0off + k]);
            ulonglong2 hb = *reinterpret_cast<const ulonglong2*>(&sm[h1off + k]);
            fma2(ar0, ha.x, vr.x); fma2(ar0, ha.y, vr.y);
            fma2(az0, ha.x, vz.x); fma2(az0, ha.y, vz.y);
            fma2(an0, ha.x, vn.x); fma2(an0, ha.y, vn.y);
            fma2(ar1, hb.x, vr.x); fma2(ar1, hb.y, vr.y);
            fma2(az1, hb.x, vz.x); fma2(az1, hb.y, vz.y);
            fma2(an1, hb.x, vn.x); fma2(an1, hb.y, vn.y);
        }

        // ---- gates / new hidden ----
        float r0 = sigf(gr0 + f2sum(ar0));
        float z0 = sigf(gz0 + f2sum(az0));
        float n0 = tanh_f(gn0 + r0 * (f2sum(an0) + bnv));
        float hold0 = sm[h0off + jbase + jl];
        float hnew0 = n0 + z0 * (hold0 - n0);

        float r1 = sigf(gr1 + f2sum(ar1));
        float z1 = sigf(gz1 + f2sum(az1));
        float n1 = tanh_f(gn1 + r1 * (f2sum(an1) + bnv));
        float hold1 = sm[h1off + jbase + jl];
        float hnew1 = n1 + z1 * (hold1 - n1);

        // ---- scatter owned slice to all 4 CTAs' next h buffer ----
        uint32_t a0 = smem_base + (uint32_t)((OFF_H + (nxt * BC + b0) * WP + jbase + jl) * 4);
        uint32_t a1 = smem_base + (uint32_t)((OFF_H + (nxt * BC + b1) * WP + jbase + jl) * 4);
        #pragma unroll
        for (int r = 0; r < CS; ++r) {
            st_remote(a0, (uint32_t)r, hnew0);
            st_remote(a1, (uint32_t)r, hnew1);
        }

        // stash prefetched x into next buffer (local)
        if (p + 1 < P_ && tid < BC * DIN)
            sm[OFF_X + (nxt * BC + pb) * 20 + pd] = xpre;

        cluster_sync_();
    }

    // final hidden lives in buffer 0 (nxt of p=511). Write owned slice.
    {
        int j = jbase + jl;
        g_enc[(cbase + b0) * H_ + j] = sm[OFF_H + b0 * WP + j];
        g_enc[(cbase + b1) * H_ + j] = sm[OFF_H + b1 * WP + j];
    }
}

// =====================================================================
// Kernel 2: twin-critic MLP  (hidden = [enc, actions, time/nts] -> 256 -> 256 -> 1)
// grid (C, B), 256 threads; weights stream from L2 (~1 MB resident).
// =====================================================================
__global__ void __launch_bounds__(256)
mlp_kernel(const float* __restrict__ actions,   // [B, A]
           const float* __restrict__ timev,     // [B]
           const float* __restrict__ W1,        // [C, INM, HID]
           const float* __restrict__ b1,        // [C, HID]
           const float* __restrict__ W2,        // [C, HID, HID]
           const float* __restrict__ b2,        // [C, HID]
           const float* __restrict__ W3,        // [C, HID, 1]
           const float* __restrict__ b3,        // [C, 1]
           const int*   __restrict__ nts,       // scalar
           float*       __restrict__ out)       // [B, C]
{
    __shared__ float hid[INM];
    __shared__ float h1s[HID_];
    __shared__ float red[8];

    const int c = blockIdx.x, b = blockIdx.y, t = threadIdx.x;

    if (t < H_)  hid[t] = g_enc[b * H_ + t];
    if (t < ACT) hid[H_ + t] = actions[b * ACT + t];
    if (t == ACT) hid[H_ + ACT] = timev[b] / (float)nts[0];
    __syncthreads();

    float a1 = b1[c * HID_ + t];
    const float* w1p = W1 + (size_t)c * INM * HID_ + t;
    #pragma unroll 5
    for (int i = 0; i < INM; ++i) a1 += hid[i] * w1p[(size_t)i * HID_];
    h1s[t] = fmaxf(a1, 0.0f);
    __syncthreads();

    float a2 = b2[c * HID_ + t];
    const float* w2p = W2 + (size_t)c * HID_ * HID_ + t;
    #pragma unroll 8
    for (int i = 0; i < HID_; ++i) a2 += h1s[i] * w2p[(size_t)i * HID_];

    float v = fmaxf(a2, 0.0f) * W3[c * HID_ + t];
    #pragma unroll
    for (int o = 16; o > 0; o >>= 1) v += __shfl_xor_sync(0xffffffffu, v, o);
    if ((t & 31) == 0) red[t >> 5] = v;
    __syncthreads();
    if (t == 0) {
        float s = 0.0f;
        #pragma unroll
        for (int w = 0; w < 8; ++w) s += red[w];
        out[b * NCRIT + c] = s + b3[c];
    }
}

// =====================================================================
extern "C" void kernel_launch(void* const* d_in, const int* in_sizes, int n_in,
                              void* d_out, int out_size)
{
    const float* particles = (const float*)d_in[0];
    const float* pw        = (const float*)d_in[1];
    const float* actions   = (const float*)d_in[2];
    const float* timev     = (const float*)d_in[3];
    const float* Wi        = (const float*)d_in[4];
    const float* bi        = (const float*)d_in[5];
    const float* Whrz      = (const float*)d_in[6];
    const float* Whn       = (const float*)d_in[7];
    const float* bn        = (const float*)d_in[8];
    const float* W1        = (const float*)d_in[9];
    const float* b1        = (const float*)d_in[10];
    const float* W2        = (const float*)d_in[11];
    const float* b2        = (const float*)d_in[12];
    const float* W3        = (const float*)d_in[13];
    const float* b3        = (const float*)d_in[14];
    const int*   nts       = (const int*)d_in[15];

    cudaFuncSetAttribute(gru_kernel,
                         cudaFuncAttributeMaxDynamicSharedMemorySize, SMEM_BYTES);

    gru_kernel<<<NCL * CS, TPB, SMEM_BYTES>>>(particles, pw, Wi, bi, Whrz, Whn, bn);

    dim3 g2(NCRIT, B_);
    mlp_kernel<<<g2, 256>>>(actions, timev, W1, b1, W2, b2, W3, b3, nts,
                            (float*)d_out);
}